// round 11
// baseline (speedup 1.0000x reference)
#include <cuda_runtime.h>
#include <cstdint>

#define T_TOK 8192
#define DIM   1024
#define DFF   4096
#define NEXP  8
#define TM    128
#define MAX_TILES (T_TOK / TM + NEXP)   // 72
#define GEMM_GRID 148
#define QDEN 32512.0f                    // 127*256 + 127 - 127 = full 2-limb range

// ======================= device scratch =======================
__device__ int8_t g_x1[(size_t)T_TOK * DIM];
__device__ int8_t g_x2[(size_t)T_TOK * DIM];
__device__ float  g_sx[T_TOK];
__device__ int8_t g_w1a[(size_t)NEXP * DFF * DIM];   // [e][n][k] limb1
__device__ int8_t g_w1b[(size_t)NEXP * DFF * DIM];   // limb2
__device__ int8_t g_w2a[(size_t)NEXP * DIM * DFF];
__device__ int8_t g_w2b[(size_t)NEXP * DIM * DFF];
__device__ float  g_sw1[NEXP * DFF], g_swi1[NEXP * DFF];
__device__ float  g_sw2[NEXP * DIM], g_swi2[NEXP * DIM];
__device__ uint32_t g_mx1[NEXP * DFF], g_mx2[NEXP * DIM];
__device__ float  g_hf[(size_t)T_TOK * DFF];         // fp32 staging of h
__device__ int8_t g_h1[(size_t)T_TOK * DFF];
__device__ int8_t g_h2[(size_t)T_TOK * DFF];
__device__ float  g_sh[T_TOK];
__device__ int    g_perm[T_TOK];
__device__ float  g_wtok[T_TOK];
__device__ int    g_eidx[T_TOK];
__device__ int    g_cnt[NEXP], g_off[NEXP], g_cur[NEXP];
__device__ int    g_tile_e[MAX_TILES], g_tile_row[MAX_TILES];
__device__ int    g_ntile;

// ======================= helpers =======================
__device__ __forceinline__ float blockmax256(float v) {
    __shared__ float red[8];
#pragma unroll
    for (int o = 16; o; o >>= 1) v = fmaxf(v, __shfl_xor_sync(0xffffffffu, v, o));
    if ((threadIdx.x & 31) == 0) red[threadIdx.x >> 5] = v;
    __syncthreads();
    float m = red[0];
#pragma unroll
    for (int i = 1; i < 8; i++) m = fmaxf(m, red[i]);
    return m;
}

__device__ __forceinline__ void q2limb(float t, int8_t& qa, int8_t& qb) {
    float a1 = rintf(t * (1.0f / 256.0f));
    a1 = fminf(127.f, fmaxf(-127.f, a1));
    float a2 = rintf(t - 256.f * a1);
    a2 = fminf(127.f, fmaxf(-128.f, a2));
    qa = (int8_t)(int)a1;
    qb = (int8_t)(int)a2;
}

__device__ __forceinline__ void quant4(float4 v, float inv, char4& c1, char4& c2) {
    int8_t a, b;
    q2limb(v.x * inv, a, b); c1.x = a; c2.x = b;
    q2limb(v.y * inv, a, b); c1.y = a; c2.y = b;
    q2limb(v.z * inv, a, b); c1.z = a; c2.z = b;
    q2limb(v.w * inv, a, b); c1.w = a; c2.w = b;
}

// ======================= small kernels =======================
__global__ void zero_kernel() {
    int t = threadIdx.x;
    if (t < NEXP) { g_cnt[t] = 0; g_cur[t] = 0; }
}

__global__ void router_kernel(const float* __restrict__ x, const float* __restrict__ gw) {
    int gtid = blockIdx.x * blockDim.x + threadIdx.x;
    int tok = gtid >> 5, lane = threadIdx.x & 31;
    if (tok >= T_TOK) return;
    const float* xr = x + (size_t)tok * DIM;
    float acc[NEXP];
#pragma unroll
    for (int e = 0; e < NEXP; e++) acc[e] = 0.f;
    for (int k = lane; k < DIM; k += 32) {
        float xv = xr[k];
        const float* g = gw + k * NEXP;
#pragma unroll
        for (int e = 0; e < NEXP; e++) acc[e] += xv * g[e];
    }
#pragma unroll
    for (int e = 0; e < NEXP; e++)
#pragma unroll
        for (int o = 16; o; o >>= 1) acc[e] += __shfl_xor_sync(0xffffffffu, acc[e], o);
    if (lane == 0) {
        float mx = acc[0]; int ai = 0;
#pragma unroll
        for (int e = 1; e < NEXP; e++) if (acc[e] > mx) { mx = acc[e]; ai = e; }
        float s = 0.f;
#pragma unroll
        for (int e = 0; e < NEXP; e++) s += expf(acc[e] - mx);
        g_wtok[tok] = 1.0f / s;
        g_eidx[tok] = ai;
        atomicAdd(&g_cnt[ai], 1);
    }
}

__global__ void offsets_kernel() {
    int off = 0, t = 0;
    for (int i = 0; i < MAX_TILES; i++) g_tile_e[i] = -1;
    for (int e = 0; e < NEXP; e++) {
        g_off[e] = off;
        int c = g_cnt[e];
        for (int i = 0; i < c; i += TM) { g_tile_e[t] = e; g_tile_row[t] = off + i; t++; }
        off += c;
    }
    g_ntile = t;
}

__global__ void scatter_kernel() {
    int t = blockIdx.x * blockDim.x + threadIdx.x;
    if (t >= T_TOK) return;
    int e = g_eidx[t];
    g_perm[g_off[e] + atomicAdd(&g_cur[e], 1)] = t;
}

// per-token-row 2-limb quantization of x
__global__ void quantx_kernel(const float* __restrict__ x) {
    int row = blockIdx.x, tid = threadIdx.x;
    float4 v = ((const float4*)(x + (size_t)row * DIM))[tid];
    float m = fmaxf(fmaxf(fabsf(v.x), fabsf(v.y)), fmaxf(fabsf(v.z), fabsf(v.w)));
    m = blockmax256(m);
    float s = (m > 0.f) ? m / QDEN : 1.f;
    float inv = (m > 0.f) ? QDEN / m : 0.f;
    if (tid == 0) g_sx[row] = s;
    char4 c1, c2;
    quant4(v, inv, c1, c2);
    ((char4*)(g_x1 + (size_t)row * DIM))[tid] = c1;
    ((char4*)(g_x2 + (size_t)row * DIM))[tid] = c2;
}

// per-h-row quantization (row length DFF, 16 elems/thread)
__global__ void quanth_kernel() {
    int row = blockIdx.x, tid = threadIdx.x;
    const float4* src = (const float4*)(g_hf + (size_t)row * DFF);
    float4 vv[4];
    float m = 0.f;
#pragma unroll
    for (int i = 0; i < 4; i++) {
        vv[i] = src[tid + i * 256];
        m = fmaxf(m, fmaxf(fmaxf(fabsf(vv[i].x), fabsf(vv[i].y)),
                           fmaxf(fabsf(vv[i].z), fabsf(vv[i].w))));
    }
    m = blockmax256(m);
    float s = (m > 0.f) ? m / QDEN : 1.f;
    float inv = (m > 0.f) ? QDEN / m : 0.f;
    if (tid == 0) g_sh[row] = s;
#pragma unroll
    for (int i = 0; i < 4; i++) {
        char4 c1, c2;
        quant4(vv[i], inv, c1, c2);
        ((char4*)(g_h1 + (size_t)row * DFF))[tid + i * 256] = c1;
        ((char4*)(g_h2 + (size_t)row * DFF))[tid + i * 256] = c2;
    }
}

__global__ void zmax_kernel() {
    int i = blockIdx.x * 256 + threadIdx.x;
    if (i < NEXP * DFF) g_mx1[i] = 0;
    if (i < NEXP * DIM) g_mx2[i] = 0;
}

template<int WSEL>
__global__ void wmax_kernel(const float* __restrict__ W) {
    constexpr int K = (WSEL == 1) ? DIM : DFF;
    constexpr int N = (WSEL == 1) ? DFF : DIM;
    uint32_t* mx = (WSEL == 1) ? g_mx1 : g_mx2;
    int n = blockIdx.x * 256 + threadIdx.x;
    int e = blockIdx.z, k0 = blockIdx.y * 512;
    const float* p = W + ((size_t)e * K + k0) * N + n;
    float m = 0.f;
#pragma unroll 8
    for (int k = 0; k < 512; k++) m = fmaxf(m, fabsf(p[(size_t)k * N]));
    atomicMax(&mx[e * N + n], __float_as_uint(m));
}

__global__ void finmax_kernel() {
    int i = blockIdx.x * 256 + threadIdx.x;
    if (i < NEXP * DFF) {
        float m = __uint_as_float(g_mx1[i]);
        g_sw1[i]  = (m > 0.f) ? m / QDEN : 1.f;
        g_swi1[i] = (m > 0.f) ? QDEN / m : 0.f;
    }
    if (i < NEXP * DIM) {
        float m = __uint_as_float(g_mx2[i]);
        g_sw2[i]  = (m > 0.f) ? m / QDEN : 1.f;
        g_swi2[i] = (m > 0.f) ? QDEN / m : 0.f;
    }
}

// transpose + quantize weights: W [e][K][N] fp32 -> limbs [e][N][K] int8
template<int WSEL>
__global__ void tq_kernel(const float* __restrict__ W) {
    constexpr int K = (WSEL == 1) ? DIM : DFF;
    constexpr int N = (WSEL == 1) ? DFF : DIM;
    int8_t* d1 = (WSEL == 1) ? g_w1a : g_w2a;
    int8_t* d2 = (WSEL == 1) ? g_w1b : g_w2b;
    const float* inv = (WSEL == 1) ? g_swi1 : g_swi2;
    __shared__ float t[32][33];
    int e = blockIdx.z;
    int n0 = blockIdx.x * 32, k0 = blockIdx.y * 32;
    const float* We = W + (size_t)e * K * N;
    int tx = threadIdx.x, ty = threadIdx.y;
#pragma unroll
    for (int i = 0; i < 4; i++)
        t[ty + i * 8][tx] = We[(size_t)(k0 + ty + i * 8) * N + n0 + tx];
    __syncthreads();
    size_t ob = (size_t)e * N * K;
#pragma unroll
    for (int i = 0; i < 4; i++) {
        int n = n0 + ty + i * 8;
        float tv = t[tx][ty + i * 8] * inv[e * N + n];
        int8_t qa, qb;
        q2limb(tv, qa, qb);
        size_t o = ob + (size_t)n * K + (k0 + tx);
        d1[o] = qa; d2[o] = qb;
    }
}

// ======================= int8 IMMA grouped GEMM (persistent, 3-stage) =======================
#define KC       64
#define RSTRIDE  80                     // 64B data + 16B pad
#define SUB_B    10240                  // one limb buffer (128 rows x 80B)
#define STAGE_B  40960                  // A1,A2,B1,B2
#define SM_AROW  122880                 // after 3 stages
#define SMEM_BYTES 123904

__device__ __forceinline__ uint32_t smem_u32(const void* p) {
    uint32_t a;
    asm("{ .reg .u64 t; cvta.to.shared.u64 t, %1; cvt.u32.u64 %0, t; }" : "=r"(a) : "l"(p));
    return a;
}
__device__ __forceinline__ void cp16(uint32_t d, const void* s) {
    asm volatile("cp.async.cg.shared.global [%0], [%1], 16;"
        :: "r"(d), "l"(__cvta_generic_to_global(s)) : "memory");
}
__device__ __forceinline__ void ldm4(uint32_t* r, uint32_t a) {
    asm volatile("ldmatrix.sync.aligned.m8n8.x4.shared.b16 {%0,%1,%2,%3}, [%4];"
        : "=r"(r[0]), "=r"(r[1]), "=r"(r[2]), "=r"(r[3]) : "r"(a));
}
__device__ __forceinline__ void mma_s8(int* c, const uint32_t* a, const uint32_t* b) {
    asm volatile("mma.sync.aligned.m16n8k32.row.col.s32.s8.s8.s32 "
        "{%0,%1,%2,%3}, {%4,%5,%6,%7}, {%8,%9}, {%0,%1,%2,%3};"
        : "+r"(c[0]), "+r"(c[1]), "+r"(c[2]), "+r"(c[3])
        : "r"(a[0]), "r"(a[1]), "r"(a[2]), "r"(a[3]), "r"(b[0]), "r"(b[1]));
}
__device__ __forceinline__ float gelu_exact(float v) {
    return 0.5f * v * (1.0f + erff(v * 0.70710678118654752f));
}
__device__ __forceinline__ float dq(int c1, int c2, float sab) {
    return sab * fmaf(65536.f, (float)c1, 256.f * (float)c2);
}

template<int MODE>  // 0: x->hf, 1: h->out
__global__ __launch_bounds__(256, 1) void gemm_q(const float* __restrict__ bias,
                                                 float* __restrict__ outp) {
    constexpr int KTOT = (MODE == 0) ? DIM : DFF;
    constexpr int NTOT = (MODE == 0) ? DFF : DIM;
    constexpr int NC = KTOT / KC;
    constexpr int NT = NTOT / 128;

    extern __shared__ __align__(128) char smem[];
    uint32_t sb = smem_u32(smem);
    int tid = threadIdx.x, wid = tid >> 5, lane = tid & 31;
    int mw = wid & 3, nw = wid >> 2;    // 4m x 2n warps, 32x64 warp tile

    const int8_t* A1 = (MODE == 0) ? g_x1 : g_h1;
    const ptrdiff_t dA2 = (MODE == 0) ? (g_x2 - g_x1) : (g_h2 - g_h1);
    const int8_t* WB = (MODE == 0) ? g_w1a : g_w2a;
    const ptrdiff_t dB2 = (MODE == 0) ? (g_w1b - g_w1a) : (g_w2b - g_w2a);
    const float* sN = (MODE == 0) ? g_sw1 : g_sw2;

    const int8_t** Ar = (const int8_t**)(smem + SM_AROW);

    uint32_t aoff = (uint32_t)((lane & 15) * RSTRIDE + (lane >> 4) * 16);
    uint32_t boff = (uint32_t)(((lane & 7) + ((lane >> 4) & 1) * 8) * RSTRIDE + ((lane >> 3) & 1) * 16);

    int nitems = g_ntile * NT;

    for (int item = blockIdx.x; item < nitems; item += GEMM_GRID) {
        int ti = item / NT;
        int nbase = (item - ti * NT) * 128;
        int e = g_tile_e[ti];
        int row0 = g_tile_row[ti];
        int rend = g_off[e] + g_cnt[e];

        __syncthreads();
        if (tid < 128) {
            int r = row0 + tid;
            int rc = (r < rend) ? r : (rend - 1);
            int src = (MODE == 0) ? g_perm[rc] : rc;
            Ar[tid] = A1 + (size_t)src * KTOT;
        }
        __syncthreads();

        const int8_t* Be = WB + ((size_t)e * NTOT + nbase) * KTOT;

        int acc1[2][8][4], acc2[2][8][4];
#pragma unroll
        for (int i = 0; i < 2; i++)
#pragma unroll
            for (int j = 0; j < 8; j++)
#pragma unroll
                for (int q = 0; q < 4; q++) { acc1[i][j][q] = 0; acc2[i][j][q] = 0; }

        auto issue = [&](int p, int kt) {
            uint32_t base = sb + p * STAGE_B;
#pragma unroll
            for (int i = 0; i < 8; i++) {
                int buf = i >> 1;                     // 0:A1 1:A2 2:B1 3:B2
                int idx = (i & 1) * 256 + tid;        // 0..511
                int r = idx >> 2, c = idx & 3;
                const int8_t* s;
                if (buf == 0)      s = Ar[r] + kt + c * 16;
                else if (buf == 1) s = Ar[r] + dA2 + kt + c * 16;
                else if (buf == 2) s = Be + (size_t)r * KTOT + kt + c * 16;
                else               s = Be + dB2 + (size_t)r * KTOT + kt + c * 16;
                cp16(base + buf * SUB_B + r * RSTRIDE + c * 16, s);
            }
            asm volatile("cp.async.commit_group;" ::: "memory");
        };

        issue(0, 0);
        issue(1, KC);

        for (int kc = 0; kc < NC; kc++) {
            int p = kc % 3;
            asm volatile("cp.async.wait_group 1;" ::: "memory");
            __syncthreads();
            if (kc + 2 < NC) issue((kc + 2) % 3, (kc + 2) * KC);

            uint32_t ab = sb + p * STAGE_B;
            uint32_t bb = ab + 2 * SUB_B;
#pragma unroll
            for (int ks = 0; ks < 2; ks++) {
                uint32_t kb = ks * 32;
                uint32_t a0 = ab + (uint32_t)(mw * 32) * RSTRIDE + kb + aoff;
                uint32_t a1f[2][4], a2f[2][4];
                ldm4(a1f[0], a0);
                ldm4(a1f[1], a0 + 16 * RSTRIDE);
                ldm4(a2f[0], a0 + SUB_B);
                ldm4(a2f[1], a0 + SUB_B + 16 * RSTRIDE);
#pragma unroll
                for (int jj = 0; jj < 4; jj++) {
                    uint32_t b0 = bb + (uint32_t)(nw * 64 + jj * 16) * RSTRIDE + kb + boff;
                    uint32_t b1f[4], b2f[4];
                    ldm4(b1f, b0);
                    ldm4(b2f, b0 + SUB_B);
#pragma unroll
                    for (int i = 0; i < 2; i++) {
                        mma_s8(acc1[i][2 * jj],     a1f[i], b1f);
                        mma_s8(acc1[i][2 * jj + 1], a1f[i], b1f + 2);
                    }
#pragma unroll
                    for (int i = 0; i < 2; i++) {
                        mma_s8(acc2[i][2 * jj],     a1f[i], b2f);
                        mma_s8(acc2[i][2 * jj + 1], a1f[i], b2f + 2);
                    }
#pragma unroll
                    for (int i = 0; i < 2; i++) {
                        mma_s8(acc2[i][2 * jj],     a2f[i], b1f);
                        mma_s8(acc2[i][2 * jj + 1], a2f[i], b1f + 2);
                    }
                }
            }
        }

        // ---------------- epilogue ----------------
        int rbase = row0 + mw * 32;
#pragma unroll
        for (int i = 0; i < 2; i++) {
            int r1 = rbase + i * 16 + (lane >> 2);
            int r2 = r1 + 8;
            bool ok1 = r1 < rend, ok2 = r2 < rend;
            float sa1 = 0.f, sa2 = 0.f, wg1 = 0.f, wg2 = 0.f;
            int tok1 = 0, tok2 = 0;
            if (MODE == 0) {
                if (ok1) sa1 = g_sx[g_perm[r1]];
                if (ok2) sa2 = g_sx[g_perm[r2]];
            } else {
                if (ok1) { sa1 = g_sh[r1]; tok1 = g_perm[r1]; wg1 = g_wtok[tok1]; }
                if (ok2) { sa2 = g_sh[r2]; tok2 = g_perm[r2]; wg2 = g_wtok[tok2]; }
            }
#pragma unroll
            for (int j = 0; j < 8; j++) {
                int n = nbase + nw * 64 + j * 8 + (lane & 3) * 2;
                float2 sbv = *(const float2*)(sN + e * NTOT + n);
                float2 bv  = *(const float2*)(bias + (size_t)e * NTOT + n);
                if (MODE == 0) {
                    if (ok1) {
                        float v0 = dq(acc1[i][j][0], acc2[i][j][0], sa1 * sbv.x) + bv.x;
                        float v1 = dq(acc1[i][j][1], acc2[i][j][1], sa1 * sbv.y) + bv.y;
                        float2 ov = make_float2(gelu_exact(v0), gelu_exact(v1));
                        *(float2*)(g_hf + (size_t)r1 * DFF + n) = ov;
                    }
                    if (ok2) {
                        float v0 = dq(acc1[i][j][2], acc2[i][j][2], sa2 * sbv.x) + bv.x;
                        float v1 = dq(acc1[i][j][3], acc2[i][j][3], sa2 * sbv.y) + bv.y;
                        float2 ov = make_float2(gelu_exact(v0), gelu_exact(v1));
                        *(float2*)(g_hf + (size_t)r2 * DFF + n) = ov;
                    }
                } else {
                    if (ok1) {
                        float2 ov;
                        ov.x = wg1 * (dq(acc1[i][j][0], acc2[i][j][0], sa1 * sbv.x) + bv.x);
                        ov.y = wg1 * (dq(acc1[i][j][1], acc2[i][j][1], sa1 * sbv.y) + bv.y);
                        *(float2*)(outp + (size_t)tok1 * DIM + n) = ov;
                    }
                    if (ok2) {
                        float2 ov;
                        ov.x = wg2 * (dq(acc1[i][j][2], acc2[i][j][2], sa2 * sbv.x) + bv.x);
                        ov.y = wg2 * (dq(acc1[i][j][3], acc2[i][j][3], sa2 * sbv.y) + bv.y);
                        *(float2*)(outp + (size_t)tok2 * DIM + n) = ov;
                    }
                }
            }
        }
    }
}

// ======================= launch =======================
extern "C" void kernel_launch(void* const* d_in, const int* in_sizes, int n_in,
                              void* d_out, int out_size) {
    const float* x      = (const float*)d_in[0];
    const float* gate_w = (const float*)d_in[1];
    const float* w1     = (const float*)d_in[2];
    const float* b1     = (const float*)d_in[3];
    const float* w2     = (const float*)d_in[4];
    const float* b2     = (const float*)d_in[5];
    float* out = (float*)d_out;

    cudaFuncSetAttribute(gemm_q<0>, cudaFuncAttributeMaxDynamicSharedMemorySize, SMEM_BYTES);
    cudaFuncSetAttribute(gemm_q<1>, cudaFuncAttributeMaxDynamicSharedMemorySize, SMEM_BYTES);

    zero_kernel<<<1, 32>>>();
    router_kernel<<<T_TOK / 8, 256>>>(x, gate_w);
    offsets_kernel<<<1, 1>>>();
    scatter_kernel<<<T_TOK / 256, 256>>>();

    quantx_kernel<<<T_TOK, 256>>>(x);
    zmax_kernel<<<(NEXP * DFF + 255) / 256, 256>>>();
    wmax_kernel<1><<<dim3(DFF / 256, DIM / 512, NEXP), 256>>>(w1);
    wmax_kernel<2><<<dim3(DIM / 256, DFF / 512, NEXP), 256>>>(w2);
    finmax_kernel<<<(NEXP * DFF + 255) / 256, 256>>>();
    tq_kernel<1><<<dim3(DFF / 32, DIM / 32, NEXP), dim3(32, 8)>>>(w1);
    tq_kernel<2><<<dim3(DIM / 32, DFF / 32, NEXP), dim3(32, 8)>>>(w2);

    gemm_q<0><<<GEMM_GRID, 256, SMEM_BYTES>>>(b1, nullptr);
    quanth_kernel<<<T_TOK, 256>>>();
    gemm_q<1><<<GEMM_GRID, 256, SMEM_BYTES>>>(b2, out);
}

// round 15
// speedup vs baseline: 2.5803x; 2.5803x over previous
#include <cuda_runtime.h>
#include <cuda_bf16.h>
#include <cstdint>

#define T_TOK 8192
#define DIM   1024
#define DFF   4096
#define NEXP  8
#define TM    128
#define MAX_TILES (T_TOK / TM + NEXP)   // 72
#define GEMM_GRID 296

// ======================= device scratch =======================
__device__ __nv_bfloat16 g_xhi[(size_t)T_TOK * DIM];
__device__ __nv_bfloat16 g_xlo[(size_t)T_TOK * DIM];
__device__ __nv_bfloat16 g_hhi[(size_t)T_TOK * DFF];
__device__ __nv_bfloat16 g_hlo[(size_t)T_TOK * DFF];
__device__ int   g_perm[T_TOK];
__device__ float g_wtok[T_TOK];
__device__ int   g_eidx[T_TOK];
__device__ int   g_cnt[NEXP], g_off[NEXP], g_cur[NEXP];
__device__ int   g_tile_e[MAX_TILES], g_tile_row[MAX_TILES];
__device__ int   g_ntile;

// ======================= small kernels =======================
__global__ void zero_kernel() {
    int t = threadIdx.x;
    if (t < NEXP) { g_cnt[t] = 0; g_cur[t] = 0; }
}

__global__ void router_kernel(const float* __restrict__ x, const float* __restrict__ gw) {
    int gtid = blockIdx.x * blockDim.x + threadIdx.x;
    int tok = gtid >> 5, lane = threadIdx.x & 31;
    if (tok >= T_TOK) return;
    const float* xr = x + (size_t)tok * DIM;
    float acc[NEXP];
#pragma unroll
    for (int e = 0; e < NEXP; e++) acc[e] = 0.f;
    for (int k = lane; k < DIM; k += 32) {
        float xv = xr[k];
        const float* g = gw + k * NEXP;
#pragma unroll
        for (int e = 0; e < NEXP; e++) acc[e] += xv * g[e];
    }
#pragma unroll
    for (int e = 0; e < NEXP; e++)
#pragma unroll
        for (int o = 16; o; o >>= 1) acc[e] += __shfl_xor_sync(0xffffffffu, acc[e], o);
    if (lane == 0) {
        float mx = acc[0]; int ai = 0;
#pragma unroll
        for (int e = 1; e < NEXP; e++) if (acc[e] > mx) { mx = acc[e]; ai = e; }
        float s = 0.f;
#pragma unroll
        for (int e = 0; e < NEXP; e++) s += expf(acc[e] - mx);
        g_wtok[tok] = 1.0f / s;
        g_eidx[tok] = ai;
        atomicAdd(&g_cnt[ai], 1);
    }
}

__global__ void offsets_kernel() {
    int off = 0, t = 0;
    for (int i = 0; i < MAX_TILES; i++) g_tile_e[i] = -1;
    for (int e = 0; e < NEXP; e++) {
        g_off[e] = off;
        int c = g_cnt[e];
        for (int i = 0; i < c; i += TM) { g_tile_e[t] = e; g_tile_row[t] = off + i; t++; }
        off += c;
    }
    g_ntile = t;
}

__global__ void scatter_kernel() {
    int t = blockIdx.x * blockDim.x + threadIdx.x;
    if (t >= T_TOK) return;
    int e = g_eidx[t];
    g_perm[g_off[e] + atomicAdd(&g_cur[e], 1)] = t;
}

__global__ void convx_kernel(const float* __restrict__ x) {
    int i = blockIdx.x * 256 + threadIdx.x;
    if (i >= T_TOK * DIM / 4) return;
    float4 v = ((const float4*)x)[i];
    float f[4] = {v.x, v.y, v.z, v.w};
    __nv_bfloat162* hp = (__nv_bfloat162*)g_xhi + i * 2;
    __nv_bfloat162* lp = (__nv_bfloat162*)g_xlo + i * 2;
    __nv_bfloat16 h[4]; __nv_bfloat16 l[4];
#pragma unroll
    for (int t = 0; t < 4; t++) {
        h[t] = __float2bfloat16(f[t]);
        l[t] = __float2bfloat16(f[t] - __bfloat162float(h[t]));
    }
    hp[0] = __halves2bfloat162(h[0], h[1]); hp[1] = __halves2bfloat162(h[2], h[3]);
    lp[0] = __halves2bfloat162(l[0], l[1]); lp[1] = __halves2bfloat162(l[2], l[3]);
}

// ======================= HMMA grouped GEMM (persistent, B converted in-kernel) =======================
// A limbs: bf16 hi/lo, 128 rows x 32 halves, 80B stride.
// B: fp32 [k32][n128] staged raw (64B/thread, 16B-aligned), converted in-kernel to
//    bf16 limbs in [k][n] layout (272B row stride), consumed via ldmatrix.trans.
#define KC       32
#define A_RS     80
#define B_RS     272
#define OFF_ALO  10240
#define OFF_BHI  20480
#define STAGE_BF 37888                   // A hi/lo (20480) + B hi/lo (2*8704)
#define F32_BASE 75776
#define F32_STAGE 16384                  // 256 threads x 64B
#define SM_AROW  108544                  // 128 x 8B pointers
#define SMEM_BYTES 109568

__device__ __forceinline__ uint32_t smem_u32(const void* p) {
    uint32_t a;
    asm("{ .reg .u64 t; cvta.to.shared.u64 t, %1; cvt.u32.u64 %0, t; }" : "=r"(a) : "l"(p));
    return a;
}
__device__ __forceinline__ void cp16(uint32_t d, const void* s) {
    asm volatile("cp.async.cg.shared.global [%0], [%1], 16;"
        :: "r"(d), "l"(__cvta_generic_to_global(s)) : "memory");
}
__device__ __forceinline__ void ldm4(uint32_t* r, uint32_t a) {
    asm volatile("ldmatrix.sync.aligned.m8n8.x4.shared.b16 {%0,%1,%2,%3}, [%4];"
        : "=r"(r[0]), "=r"(r[1]), "=r"(r[2]), "=r"(r[3]) : "r"(a));
}
__device__ __forceinline__ void ldm4t(uint32_t* r, uint32_t a) {
    asm volatile("ldmatrix.sync.aligned.m8n8.x4.trans.shared.b16 {%0,%1,%2,%3}, [%4];"
        : "=r"(r[0]), "=r"(r[1]), "=r"(r[2]), "=r"(r[3]) : "r"(a));
}
__device__ __forceinline__ void mma_bf16(float* c, const uint32_t* a, const uint32_t* b) {
    asm volatile("mma.sync.aligned.m16n8k16.row.col.f32.bf16.bf16.f32 "
        "{%0,%1,%2,%3}, {%4,%5,%6,%7}, {%8,%9}, {%0,%1,%2,%3};"
        : "+f"(c[0]), "+f"(c[1]), "+f"(c[2]), "+f"(c[3])
        : "r"(a[0]), "r"(a[1]), "r"(a[2]), "r"(a[3]), "r"(b[0]), "r"(b[1]));
}
__device__ __forceinline__ float gelu_exact(float v) {
    return 0.5f * v * (1.0f + erff(v * 0.70710678118654752f));
}

template<int MODE>  // 0: x->h, 1: h->out
__global__ __launch_bounds__(256, 2) void gemm_tc(const float* __restrict__ Wf,
                                                  const float* __restrict__ bias,
                                                  float* __restrict__ outp) {
    constexpr int KTOT = (MODE == 0) ? DIM : DFF;
    constexpr int NTOT = (MODE == 0) ? DFF : DIM;
    constexpr int NC = KTOT / KC;
    constexpr int NT = NTOT / 128;

    extern __shared__ __align__(128) char smem[];
    uint32_t sb = smem_u32(smem);
    int tid = threadIdx.x, wid = tid >> 5, lane = tid & 31;
    int mw = wid & 3, nw = wid >> 2;     // 4m x 2n warps, 32x64 warp tile

    const __nv_bfloat16* Ahi = (MODE == 0) ? g_xhi : g_hhi;
    const ptrdiff_t dAlo = (MODE == 0) ? (g_xlo - g_xhi) : (g_hlo - g_hhi);

    const __nv_bfloat16** Ar = (const __nv_bfloat16**)(smem + SM_AROW);

    uint32_t aoff = (uint32_t)((lane & 15) * A_RS + (lane >> 4) * 16);
    // B .trans tiles: lanes 0-7 k0-7/n0, 8-15 k8-15/n0, 16-23 k0-7/n8, 24-31 k8-15/n8
    uint32_t boff = (uint32_t)(((lane & 7) + ((lane >> 3) & 1) * 8) * B_RS + (lane >> 4) * 16);

    int bk = tid >> 3;                   // 0..31 (k row in chunk)
    int bn = tid & 7;                    // 0..7  (n segment of 16 floats)

    int nitems = g_ntile * NT;

    for (int item = blockIdx.x; item < nitems; item += GEMM_GRID) {
        int ti = item / NT;
        int nbase = (item - ti * NT) * 128;
        int e = g_tile_e[ti];
        int row0 = g_tile_row[ti];
        int rend = g_off[e] + g_cnt[e];

        if (tid < 128) {
            int r = row0 + tid;
            int rc = (r < rend) ? r : (rend - 1);
            int src = (MODE == 0) ? g_perm[rc] : rc;
            Ar[tid] = Ahi + (size_t)src * KTOT;
        }
        __syncthreads();

        const float* Be = Wf + (size_t)e * KTOT * NTOT + nbase;

        float acc[2][8][4];
#pragma unroll
        for (int i = 0; i < 2; i++)
#pragma unroll
            for (int j = 0; j < 8; j++)
#pragma unroll
                for (int q = 0; q < 4; q++) acc[i][j][q] = 0.f;

        // issue A-limb cp.async + raw fp32 B cp.async for chunk at kt into stage p
        auto issue = [&](int p, int kt) {
            uint32_t abase = sb + p * STAGE_BF;
#pragma unroll
            for (int i = 0; i < 4; i++) {
                int idx = tid + i * 256;                  // 0..1023
                int r = (idx >> 2) & 127, c = idx & 3, half = idx >> 9;
                const __nv_bfloat16* s = Ar[r] + (half ? dAlo : 0) + kt + c * 8;
                cp16(abase + half * OFF_ALO + r * A_RS + c * 16, s);
            }
            uint32_t fbase = sb + F32_BASE + p * F32_STAGE + tid * 64;
            const float* bs = Be + (size_t)(kt + bk) * NTOT + bn * 16;
#pragma unroll
            for (int j = 0; j < 4; j++) cp16(fbase + j * 16, bs + j * 4);
            asm volatile("cp.async.commit_group;" ::: "memory");
        };

        // convert staged fp32 B chunk in stage p to bf16 limbs
        auto convertB = [&](int p) {
            const float4* fp = (const float4*)(smem + F32_BASE + p * F32_STAGE + tid * 64);
            float4 v[4];
#pragma unroll
            for (int j = 0; j < 4; j++) v[j] = fp[j];
            union { ushort u[16]; uint4 q[2]; } H, L;
#pragma unroll
            for (int j = 0; j < 4; j++) {
                float f[4] = {v[j].x, v[j].y, v[j].z, v[j].w};
#pragma unroll
                for (int t = 0; t < 4; t++) {
                    __nv_bfloat16 h = __float2bfloat16(f[t]);
                    float rv = f[t] - __bfloat162float(h);
                    H.u[j * 4 + t] = __bfloat16_as_ushort(h);
                    L.u[j * 4 + t] = __bfloat16_as_ushort(__float2bfloat16(rv));
                }
            }
            char* dst = smem + p * STAGE_BF + OFF_BHI + bk * B_RS + bn * 32;
            *(uint4*)(dst) = H.q[0];
            *(uint4*)(dst + 16) = H.q[1];
            *(uint4*)(dst + 8704) = L.q[0];
            *(uint4*)(dst + 8704 + 16) = L.q[1];
        };

        issue(0, 0);

        for (int kc = 0; kc < NC; kc++) {
            int p = kc & 1;
            asm volatile("cp.async.wait_group 0;" ::: "memory");
            convertB(p);
            __syncthreads();
            if (kc + 1 < NC) issue(p ^ 1, (kc + 1) * KC);

            uint32_t ab = sb + p * STAGE_BF;
            uint32_t bb = ab + OFF_BHI;
#pragma unroll
            for (int ks = 0; ks < 2; ks++) {
                uint32_t a0 = ab + (uint32_t)(mw * 32) * A_RS + ks * 32 + aoff;
                uint32_t ah[2][4], al[2][4];
                ldm4(ah[0], a0);
                ldm4(ah[1], a0 + 16 * A_RS);
                ldm4(al[0], a0 + OFF_ALO);
                ldm4(al[1], a0 + OFF_ALO + 16 * A_RS);
#pragma unroll
                for (int jj = 0; jj < 4; jj++) {
                    uint32_t b0 = bb + (uint32_t)(ks * 16) * B_RS
                                + (uint32_t)(nw * 64 + jj * 16) * 2 + boff;
                    uint32_t bh[4], bl[4];
                    ldm4t(bh, b0);
                    ldm4t(bl, b0 + 8704);
#pragma unroll
                    for (int i = 0; i < 2; i++) {
                        mma_bf16(acc[i][2 * jj],     ah[i], bh);
                        mma_bf16(acc[i][2 * jj + 1], ah[i], bh + 2);
                    }
#pragma unroll
                    for (int i = 0; i < 2; i++) {
                        mma_bf16(acc[i][2 * jj],     al[i], bh);
                        mma_bf16(acc[i][2 * jj + 1], al[i], bh + 2);
                    }
#pragma unroll
                    for (int i = 0; i < 2; i++) {
                        mma_bf16(acc[i][2 * jj],     ah[i], bl);
                        mma_bf16(acc[i][2 * jj + 1], ah[i], bl + 2);
                    }
                }
            }
        }

        // ---------------- epilogue ----------------
        int rbase = row0 + mw * 32;
#pragma unroll
        for (int i = 0; i < 2; i++) {
            int r1 = rbase + i * 16 + (lane >> 2);
            int r2 = r1 + 8;
            bool ok1 = r1 < rend, ok2 = r2 < rend;
            int tok1 = 0, tok2 = 0; float wg1 = 0.f, wg2 = 0.f;
            if (MODE == 1) {
                if (ok1) { tok1 = g_perm[r1]; wg1 = g_wtok[tok1]; }
                if (ok2) { tok2 = g_perm[r2]; wg2 = g_wtok[tok2]; }
            }
#pragma unroll
            for (int j = 0; j < 8; j++) {
                int n = nbase + nw * 64 + j * 8 + (lane & 3) * 2;
                float2 bv = *(const float2*)(bias + (size_t)e * NTOT + n);
                if (MODE == 0) {
                    if (ok1) {
                        float v0 = gelu_exact(acc[i][j][0] + bv.x);
                        float v1 = gelu_exact(acc[i][j][1] + bv.y);
                        __nv_bfloat16 h0 = __float2bfloat16(v0), h1 = __float2bfloat16(v1);
                        __nv_bfloat16 l0 = __float2bfloat16(v0 - __bfloat162float(h0));
                        __nv_bfloat16 l1 = __float2bfloat16(v1 - __bfloat162float(h1));
                        *(__nv_bfloat162*)(g_hhi + (size_t)r1 * DFF + n) = __halves2bfloat162(h0, h1);
                        *(__nv_bfloat162*)(g_hlo + (size_t)r1 * DFF + n) = __halves2bfloat162(l0, l1);
                    }
                    if (ok2) {
                        float v0 = gelu_exact(acc[i][j][2] + bv.x);
                        float v1 = gelu_exact(acc[i][j][3] + bv.y);
                        __nv_bfloat16 h0 = __float2bfloat16(v0), h1 = __float2bfloat16(v1);
                        __nv_bfloat16 l0 = __float2bfloat16(v0 - __bfloat162float(h0));
                        __nv_bfloat16 l1 = __float2bfloat16(v1 - __bfloat162float(h1));
                        *(__nv_bfloat162*)(g_hhi + (size_t)r2 * DFF + n) = __halves2bfloat162(h0, h1);
                        *(__nv_bfloat162*)(g_hlo + (size_t)r2 * DFF + n) = __halves2bfloat162(l0, l1);
                    }
                } else {
                    if (ok1) {
                        float2 ov;
                        ov.x = wg1 * (acc[i][j][0] + bv.x);
                        ov.y = wg1 * (acc[i][j][1] + bv.y);
                        *(float2*)(outp + (size_t)tok1 * DIM + n) = ov;
                    }
                    if (ok2) {
                        float2 ov;
                        ov.x = wg2 * (acc[i][j][2] + bv.x);
                        ov.y = wg2 * (acc[i][j][3] + bv.y);
                        *(float2*)(outp + (size_t)tok2 * DIM + n) = ov;
                    }
                }
            }
        }
        __syncthreads();     // all limb/f32 stages + Ar dead before next item's writes
    }
}

// ======================= launch =======================
extern "C" void kernel_launch(void* const* d_in, const int* in_sizes, int n_in,
                              void* d_out, int out_size) {
    const float* x      = (const float*)d_in[0];
    const float* gate_w = (const float*)d_in[1];
    const float* w1     = (const float*)d_in[2];
    const float* b1     = (const float*)d_in[3];
    const float* w2     = (const float*)d_in[4];
    const float* b2     = (const float*)d_in[5];
    float* out = (float*)d_out;

    cudaFuncSetAttribute(gemm_tc<0>, cudaFuncAttributeMaxDynamicSharedMemorySize, SMEM_BYTES);
    cudaFuncSetAttribute(gemm_tc<1>, cudaFuncAttributeMaxDynamicSharedMemorySize, SMEM_BYTES);

    zero_kernel<<<1, 32>>>();
    router_kernel<<<T_TOK / 8, 256>>>(x, gate_w);
    offsets_kernel<<<1, 1>>>();
    scatter_kernel<<<T_TOK / 256, 256>>>();
    convx_kernel<<<(T_TOK * DIM / 4 + 255) / 256, 256>>>(x);

    gemm_tc<0><<<GEMM_GRID, 256, SMEM_BYTES>>>(w1, b1, nullptr);
    gemm_tc<1><<<GEMM_GRID, 256, SMEM_BYTES>>>(w2, b2, out);
}